// round 16
// baseline (speedup 1.0000x reference)
#include <cuda_runtime.h>
#include <cuda_bf16.h>
#include <math.h>
#include <stdint.h>

typedef uint32_t u32;

// ---------------- scratch (device globals; no allocation) ----------------
__device__ float g_latT [256*256];
__device__ float g_craw [256*1536];
__device__ float g_x1raw[2][256*2048];
__device__ float g_y2   [2][256*256*31];
__device__ float g_abc  [2][512];
__device__ float g_st1c [2][512];
__device__ float g_st1hw[2][2][128];
__device__ float g_st2  [2][2][256];
__device__ float g_hw   [2][256*512*32];
// fragment-order bf16 operands: A split hi/lo arrays, B packed hi+lo uint4
__device__ __align__(16) u32 g_A2f [2][256*8*32*4];
__device__ __align__(16) u32 g_A2fl[2][256*8*32*4];
__device__ __align__(16) u32 g_B2p [2][512*8*32*4];
__device__ __align__(16) u32 g_A3f [2][512*16*32*4];
__device__ __align__(16) u32 g_A3fl[2][512*16*32*4];
__device__ __align__(16) u32 g_B3p [2][128*16*32*4];

__device__ __forceinline__ u32 packbf(float x, float y) {
    __nv_bfloat162 t;
    t.x = __float2bfloat16(x);
    t.y = __float2bfloat16(y);
    return *reinterpret_cast<u32*>(&t);
}
__device__ __forceinline__ void split_pair(float v0, float v1, u32& hw, u32& lw) {
    __nv_bfloat16 h0 = __float2bfloat16(v0), h1 = __float2bfloat16(v1);
    float r0 = v0 - __bfloat162float(h0), r1 = v1 - __bfloat162float(h1);
    __nv_bfloat162 th; th.x = h0; th.y = h1;
    hw = *reinterpret_cast<u32*>(&th);
    lw = packbf(r0, r1);
}
__device__ __forceinline__ void wreduce2(float& s, float& q) {
    #pragma unroll
    for (int o = 16; o > 0; o >>= 1) {
        s += __shfl_xor_sync(0xffffffffu, s, o);
        q += __shfl_xor_sync(0xffffffffu, q, o);
    }
}

#define MMA16816(c, a, b) \
    asm volatile("mma.sync.aligned.m16n8k16.row.col.f32.bf16.bf16.f32 " \
                 "{%0,%1,%2,%3}, {%4,%5,%6,%7}, {%8,%9}, {%0,%1,%2,%3};" \
                 : "+f"((c)[0]), "+f"((c)[1]), "+f"((c)[2]), "+f"((c)[3]) \
                 : "r"((a)[0]), "r"((a)[1]), "r"((a)[2]), "r"((a)[3]), \
                   "r"((b)[0]), "r"((b)[1]))

// ---------------- kernel 1: latent + prepB combo ----------------
__global__ __launch_bounds__(256) void k_combo(
    const float* __restrict__ noise, const int* __restrict__ label,
    const float* __restrict__ lin_w, const float* __restrict__ bn0_g,
    const float* __restrict__ bn0_b, const float* __restrict__ emb,
    const float* __restrict__ W2h, const float* __restrict__ W2w,
    const float* __restrict__ W3h, const float* __restrict__ W3w)
{
    const int bid = blockIdx.x, tid = threadIdx.x;
    if (bid < 256) {
        if (bid == 0) {   // zero all stat accumulators
            float* p1 = (float*)g_st1c;
            for (int i = tid; i < 1024; i += 256) p1[i] = 0.f;
            float* p2 = (float*)g_st1hw;
            for (int i = tid; i < 512; i += 256) p2[i] = 0.f;
            float* p3 = (float*)g_st2;
            for (int i = tid; i < 1024; i += 256) p3[i] = 0.f;
        }
        const int ch = bid, b = tid;
        if (ch >= 128) {
            g_latT[ch*256 + b] = emb[label[b]*128 + (ch - 128)];
            return;
        }
        __shared__ float wsm[100];
        if (b < 100) wsm[b] = lin_w[ch*100 + b];
        __syncthreads();
        const float* nr = noise + b*100;
        float z = 0.f;
        #pragma unroll 4
        for (int i = 0; i < 100; i++) z += nr[i]*wsm[i];
        float s = z, q = z*z;
        wreduce2(s, q);
        __shared__ float sp[8], qp[8];
        if ((b & 31) == 0) { sp[b >> 5] = s; qp[b >> 5] = q; }
        __syncthreads();
        float ts = 0.f, tq = 0.f;
        #pragma unroll
        for (int i = 0; i < 8; i++) { ts += sp[i]; tq += qp[i]; }
        float m   = ts*(1.f/256.f);
        float var = tq*(1.f/256.f) - m*m;
        float a   = bn0_g[ch]*rsqrtf(var + 1e-5f);
        float y   = (z - m)*a + bn0_b[ch];
        g_latT[ch*256 + b] = (y >= 0.f) ? y : 0.01f*y;
        return;
    }
    // ---- prepB: weights -> packed fragment order (coalesced reads) ----
    int gid = (bid - 256)*256 + tid;
    if (gid < 524288) {                       // W2: 2 br x 64 cp x 4096 n
        int br = gid >> 18, rem = gid & 262143;
        int cp = rem >> 12, n = rem & 4095;
        const float* W = br ? W2w : W2h;
        float v0 = W[(2*cp)*4096 + n];
        float v1 = W[(2*cp + 1)*4096 + n];
        u32 hw, lw; split_pair(v0, v1, hw, lw);
        int ni = n >> 3, ks = cp >> 3, cpl = cp & 7;
        int lane = (n & 7)*4 + (cpl & 3), w = cpl >> 2;
        int base = ((ni*8 + ks)*32 + lane)*4;
        g_B2p[br][base + w]     = hw;
        g_B2p[br][base + 2 + w] = lw;
    } else {                                  // W3: 2 br x 128 cp x 1024 n
        int g2 = gid - 524288;
        int br = g2 >> 17, rem = g2 & 131071;
        int cp = rem >> 10, n = rem & 1023;
        const float* W = br ? W3w : W3h;
        float v0 = W[(2*cp)*1024 + n];
        float v1 = W[(2*cp + 1)*1024 + n];
        u32 hw, lw; split_pair(v0, v1, hw, lw);
        int ni = n >> 3, ks = cp >> 3, cpl = cp & 7;
        int lane = (n & 7)*4 + (cpl & 3), w = cpl >> 2;
        int base = ((ni*16 + ks)*32 + lane)*4;
        g_B3p[br][base + w]     = hw;
        g_B3p[br][base + 2 + w] = lw;
    }
}

// ---------------- kernel 2: conv1 GEMMs + fused BN stat partials ----------------
__global__ __launch_bounds__(256) void k_gemm1m(
    const float* __restrict__ Wc, const float* __restrict__ Wh,
    const float* __restrict__ Ww)
{
    const int z = blockIdx.z;
    int N; const float* W; float* O;
    if (z == 2) {
        if (blockIdx.x >= 24) return;
        N = 1536; W = Wc; O = g_craw;
    } else {
        N = 2048; W = z ? Ww : Wh; O = g_x1raw[z];
    }
    const int n0 = blockIdx.x*64, b0 = blockIdx.y*64;
    const int tid = threadIdx.x, tx = tid & 15, ty = tid >> 4;
    __shared__ float Xs[16][68], Ws[16][68];
    __shared__ float cs1[64], cq1[64];
    if (tid < 64) { cs1[tid] = 0.f; cq1[tid] = 0.f; }
    float acc[4][4] = {};
    for (int k0 = 0; k0 < 256; k0 += 16) {
        __syncthreads();
        for (int i = tid; i < 1024; i += 256) {
            int k = i >> 6, c = i & 63;
            Xs[k][c] = g_latT[(k0+k)*256 + b0 + c];
            Ws[k][c] = W[(k0+k)*N + n0 + c];
        }
        __syncthreads();
        #pragma unroll
        for (int k = 0; k < 16; k++) {
            float4 x4 = *(const float4*)&Xs[k][ty*4];
            float4 w4 = *(const float4*)&Ws[k][tx*4];
            float xa[4] = {x4.x, x4.y, x4.z, x4.w};
            float wa[4] = {w4.x, w4.y, w4.z, w4.w};
            #pragma unroll
            for (int i = 0; i < 4; i++)
                #pragma unroll
                for (int j = 0; j < 4; j++) acc[i][j] += xa[i]*wa[j];
        }
    }
    #pragma unroll
    for (int i = 0; i < 4; i++) {
        float4 v = make_float4(acc[i][0], acc[i][1], acc[i][2], acc[i][3]);
        *(float4*)&O[(b0 + ty*4 + i)*N + n0 + tx*4] = v;
    }
    #pragma unroll
    for (int j = 0; j < 4; j++) {
        float s = acc[0][j] + acc[1][j] + acc[2][j] + acc[3][j];
        float q = acc[0][j]*acc[0][j] + acc[1][j]*acc[1][j]
                + acc[2][j]*acc[2][j] + acc[3][j]*acc[3][j];
        atomicAdd(&cs1[tx*4 + j], s);
        atomicAdd(&cq1[tx*4 + j], q);
    }
    __syncthreads();
    if (tid < 64) {
        int n = n0 + tid;
        if (z == 2) {
            atomicAdd(&g_st1c[0][n/3], cs1[tid]);
            atomicAdd(&g_st1c[1][n/3], cq1[tid]);
        } else {
            atomicAdd(&g_st1hw[z][0][n >> 4], cs1[tid]);
            atomicAdd(&g_st1hw[z][1][n >> 4], cq1[tid]);
        }
    }
}

// ---------------- prepA2: affine from fused stats, smem tile, fragment order --------
__global__ __launch_bounds__(256) void k_prepA2n(
    const float* __restrict__ cg, const float* __restrict__ cb,
    const float* __restrict__ hg, const float* __restrict__ hb,
    const float* __restrict__ wg, const float* __restrict__ wb)
{
    const int b = blockIdx.x, br = blockIdx.y, tid = threadIdx.x;
    if (b == 1 && br == 0) {
        for (int c = tid; c < 512; c += 256) {
            float s = g_st1c[0][c], q = g_st1c[1][c];
            const float invn = 1.f/(256.f*3.f);
            float m   = s*invn;
            float var = q*invn - m*m;
            float a   = cg[c]*rsqrtf(var + 1e-5f);
            g_abc[0][c] = a;
            g_abc[1][c] = cb[c] - m*a;
        }
    }
    __shared__ float xs[128*17];
    __shared__ float aAs[128], aSs[128];
    if (tid < 128) {
        float s = g_st1hw[br][0][tid], q = g_st1hw[br][1][tid];
        const float invn = 1.f/(256.f*16.f);
        float m   = s*invn;
        float var = q*invn - m*m;
        float gam = br ? wg[tid] : hg[tid];
        float bet = br ? wb[tid] : hb[tid];
        float a   = gam*rsqrtf(var + 1e-5f);
        aAs[tid] = a;
        aSs[tid] = bet - m*a;
    }
    for (int idx = tid; idx < 2048; idx += 256) {
        float v = g_x1raw[br][b*2048 + idx];
        xs[(idx >> 4)*17 + (idx & 15)] = v;
    }
    __syncthreads();
    const int ks = tid >> 5, lane = tid & 31;
    u32 oh[4], ol[4];
    #pragma unroll
    for (int w = 0; w < 4; w++) {
        int cpl2 = w >> 1, l3 = w & 1;
        int l   = (l3 << 3) | (lane >> 2);
        int cpl = (cpl2 << 2) | (lane & 3);
        int ci  = (ks*8 + cpl)*2;
        float v0 = fmaf(aAs[ci],   xs[ci*17 + l],     aSs[ci]);
        float v1 = fmaf(aAs[ci+1], xs[(ci+1)*17 + l], aSs[ci+1]);
        v0 = (v0 >= 0.f) ? v0 : 0.2f*v0;
        v1 = (v1 >= 0.f) ? v1 : 0.2f*v1;
        split_pair(v0, v1, oh[w], ol[w]);
    }
    int addr = ((b*8 + ks)*32 + lane)*4;
    *(uint4*)&g_A2f [br][addr] = make_uint4(oh[0], oh[1], oh[2], oh[3]);
    *(uint4*)&g_A2fl[br][addr] = make_uint4(ol[0], ol[1], ol[2], ol[3]);
}

// ---------------- conv2: fragment-direct mma.sync, N-split halves, 3 CTAs/SM --------
extern __shared__ u32 smw[];
__global__ __launch_bounds__(256, 3) void k_conv2f()
{
    const int br = blockIdx.z, nx = blockIdx.x, my = blockIdx.y;
    const int tid = threadIdx.x, lane = tid & 31, wid = tid >> 5;
    const int wm = wid >> 2, wn = wid & 3;
    const u32* __restrict__ AH = g_A2f [br];
    const u32* __restrict__ AL = g_A2fl[br];
    const u32* __restrict__ BP = g_B2p [br];
    const int mi0 = my*8 + wm*4;
    float* Cs = (float*)smw;                    // 128 x 132
    const int qr = lane >> 2, qt = lane & 3;
    #pragma unroll
    for (int half = 0; half < 2; half++) {
        const int ni0 = nx*16 + wn*4 + half*2;
        float acc[4][2][4] = {};
        #pragma unroll
        for (int ks = 0; ks < 8; ks++) {
            u32 bh[2][2], bl[2][2];
            #pragma unroll
            for (int nt = 0; nt < 2; nt++) {
                uint4 v = *(const uint4*)(BP + (((ni0+nt)*8 + ks)*32 + lane)*4);
                bh[nt][0] = v.x; bh[nt][1] = v.y;
                bl[nt][0] = v.z; bl[nt][1] = v.w;
            }
            #pragma unroll
            for (int mt = 0; mt < 4; mt++) {
                int aa = (((mi0+mt)*8 + ks)*32 + lane)*4;
                uint4 vh = *(const uint4*)(AH + aa);
                uint4 vl = *(const uint4*)(AL + aa);
                u32 ah[4] = {vh.x, vh.y, vh.z, vh.w};
                u32 al[4] = {vl.x, vl.y, vl.z, vl.w};
                #pragma unroll
                for (int nt = 0; nt < 2; nt++) {
                    MMA16816(acc[mt][nt], ah, bh[nt]);
                    MMA16816(acc[mt][nt], ah, bl[nt]);
                    MMA16816(acc[mt][nt], al, bh[nt]);
                }
            }
        }
        #pragma unroll
        for (int mt = 0; mt < 4; mt++)
            #pragma unroll
            for (int nt = 0; nt < 2; nt++) {
                int r0 = wm*64 + mt*16 + qr;
                int c0 = wn*32 + (half*2 + nt)*8 + qt*2;
                Cs[r0*132 + c0]       = acc[mt][nt][0];
                Cs[r0*132 + c0 + 1]   = acc[mt][nt][1];
                Cs[(r0+8)*132 + c0]   = acc[mt][nt][2];
                Cs[(r0+8)*132 + c0+1] = acc[mt][nt][3];
            }
    }
    __syncthreads();
    // epilogue: warp w owns output channel co_l = w; fold, write y2, stat partials.
    {
        const int co_l = wid;
        float ssum = 0.f, sq = 0.f;
        for (int i = lane; i < 248; i += 32) {
            int bl2 = i / 31, t = i - bl2*31;
            int lo = (t > 15) ? (t - 15) : 0;
            int hi = (t < 15) ? t : 15;
            float s = 0.f;
            for (int tp = lo; tp <= hi; tp++)
                s += Cs[(bl2*16 + tp)*132 + co_l*16 + (t - tp)];
            g_y2[br][((my*8 + bl2)*256 + nx*8 + co_l)*31 + t] = s;
            ssum += s; sq += s*s;
        }
        wreduce2(ssum, sq);
        if (lane == 0) {
            atomicAdd(&g_st2[br][0][nx*8 + co_l], ssum);
            atomicAdd(&g_st2[br][1][nx*8 + co_l], sq);
        }
    }
}

// ---------------- prepA3: affine from fused stats, smem tile, fragment order ------
__global__ __launch_bounds__(256) void k_prepA3n(
    const float* __restrict__ hg, const float* __restrict__ hb,
    const float* __restrict__ wg, const float* __restrict__ wb)
{
    const int b = blockIdx.x, br = blockIdx.y, tid = threadIdx.x;
    __shared__ float ys[256*33];
    __shared__ float aAs[256], aSs[256];
    {
        float s = g_st2[br][0][tid], q = g_st2[br][1][tid];
        const float inv = 1.f/(256.f*31.f);
        float m   = s*inv;
        float var = q*inv - m*m;
        float gam = br ? wg[tid] : hg[tid];
        float bet = br ? wb[tid] : hb[tid];
        float a   = gam*rsqrtf(var + 1e-5f);
        aAs[tid] = a;
        aSs[tid] = bet - m*a;
    }
    for (int idx = tid; idx < 7936; idx += 256) {
        float v = g_y2[br][b*7936 + idx];
        ys[(idx / 31)*33 + (idx % 31)] = v;
    }
    __syncthreads();
    const int lane = tid & 31;
    #pragma unroll
    for (int it = 0; it < 2; it++) {
        const int ks = (tid >> 5) + 8*it;
        #pragma unroll
        for (int mih = 0; mih < 2; mih++) {
            u32 oh[4], ol[4];
            #pragma unroll
            for (int w = 0; w < 4; w++) {
                int cpl2 = w >> 1, r3 = w & 1;
                int r   = (r3 << 3) | (lane >> 2);
                int tp  = (mih << 4) | r;
                int cpl = (cpl2 << 2) | (lane & 3);
                int ci  = (ks*8 + cpl)*2;
                float v0 = 0.f, v1 = 0.f;
                if (tp < 31) {
                    v0 = fmaf(aAs[ci],   ys[ci*33 + tp],     aSs[ci]);
                    v1 = fmaf(aAs[ci+1], ys[(ci+1)*33 + tp], aSs[ci+1]);
                    v0 = (v0 >= 0.f) ? v0 : 0.2f*v0;
                    v1 = (v1 >= 0.f) ? v1 : 0.2f*v1;
                }
                split_pair(v0, v1, oh[w], ol[w]);
            }
            int mi = b*2 + mih;
            int addr = ((mi*16 + ks)*32 + lane)*4;
            *(uint4*)&g_A3f [br][addr] = make_uint4(oh[0], oh[1], oh[2], oh[3]);
            *(uint4*)&g_A3fl[br][addr] = make_uint4(ol[0], ol[1], ol[2], ol[3]);
        }
    }
}

// ---------------- conv3: fragment-direct mma.sync, N-split halves, 3 CTAs/SM ------
__global__ __launch_bounds__(256, 3) void k_conv3f(
    const float* __restrict__ bh3, const float* __restrict__ bw3)
{
    const int br = blockIdx.z, nx = blockIdx.x, my = blockIdx.y;
    const float* __restrict__ bias = br ? bw3 : bh3;
    const int tid = threadIdx.x, lane = tid & 31, wid = tid >> 5;
    const int wm = wid >> 2, wn = wid & 3;
    const u32* __restrict__ AH = g_A3f [br];
    const u32* __restrict__ AL = g_A3fl[br];
    const u32* __restrict__ BP = g_B3p [br];
    const int mi0 = my*8 + wm*4;
    float* Cs = (float*)smw;                    // 128 x 132
    const int qr = lane >> 2, qt = lane & 3;
    #pragma unroll
    for (int half = 0; half < 2; half++) {
        const int ni0 = nx*16 + wn*4 + half*2;
        float acc[4][2][4] = {};
        #pragma unroll
        for (int ks = 0; ks < 16; ks++) {
            u32 bh[2][2], bl[2][2];
            #pragma unroll
            for (int nt = 0; nt < 2; nt++) {
                uint4 v = *(const uint4*)(BP + (((ni0+nt)*16 + ks)*32 + lane)*4);
                bh[nt][0] = v.x; bh[nt][1] = v.y;
                bl[nt][0] = v.z; bl[nt][1] = v.w;
            }
            #pragma unroll
            for (int mt = 0; mt < 4; mt++) {
                int aa = (((mi0+mt)*16 + ks)*32 + lane)*4;
                uint4 vh = *(const uint4*)(AH + aa);
                uint4 vl = *(const uint4*)(AL + aa);
                u32 ah[4] = {vh.x, vh.y, vh.z, vh.w};
                u32 al[4] = {vl.x, vl.y, vl.z, vl.w};
                #pragma unroll
                for (int nt = 0; nt < 2; nt++) {
                    MMA16816(acc[mt][nt], ah, bh[nt]);
                    MMA16816(acc[mt][nt], ah, bl[nt]);
                    MMA16816(acc[mt][nt], al, bh[nt]);
                }
            }
        }
        #pragma unroll
        for (int mt = 0; mt < 4; mt++)
            #pragma unroll
            for (int nt = 0; nt < 2; nt++) {
                int r0 = wm*64 + mt*16 + qr;
                int c0 = wn*32 + (half*2 + nt)*8 + qt*2;
                Cs[r0*132 + c0]       = acc[mt][nt][0];
                Cs[r0*132 + c0 + 1]   = acc[mt][nt][1];
                Cs[(r0+8)*132 + c0]   = acc[mt][nt][2];
                Cs[(r0+8)*132 + c0+1] = acc[mt][nt][3];
            }
    }
    __syncthreads();
    for (int i = 0; i < 32; i++) {
        int idx = tid + i*256;                  // 8192 outputs
        int t = idx & 31, co_l = (idx >> 5) & 63, bl2 = idx >> 11;
        int row = bl2*32 + t;
        float v = Cs[row*132 + 2*co_l];
        if (t > 0) v += Cs[(row-1)*132 + 2*co_l + 1];
        v += bias[nx*64 + co_l];
        g_hw[br][((my*4 + bl2)*512 + nx*64 + co_l)*32 + t] = tanhf(v);
    }
}

// ---------------- kernel: final einsum ----------------
__global__ __launch_bounds__(256) void k_final(const float* __restrict__ coef,
                                               float* __restrict__ out)
{
    const int b = blockIdx.x, tid = threadIdx.x;
    __shared__ __align__(16) float4 cs[128];
    __shared__ __align__(16) float  hs [128*32];
    __shared__ __align__(16) float  ws2[128*32];
    const int p0 = tid*4, hh = p0 >> 5, ww0 = p0 & 31;
    float acc[4][3];
    #pragma unroll
    for (int i = 0; i < 4; i++)
        #pragma unroll
        for (int c = 0; c < 3; c++) acc[i][c] = 0.f;
    for (int chk = 0; chk < 4; chk++) {
        const int r0 = chk*128;
        __syncthreads();
        if (tid < 128) {
            const int r = r0 + tid;
            const float* cp = g_craw + b*1536 + r*3;
            float a = g_abc[0][r], sh = g_abc[1][r];
            float cf = coef[r];
            float v0 = fmaf(a, cp[0], sh); v0 = (v0 >= 0.f) ? v0 : 0.2f*v0;
            float v1 = fmaf(a, cp[1], sh); v1 = (v1 >= 0.f) ? v1 : 0.2f*v1;
            float v2 = fmaf(a, cp[2], sh); v2 = (v2 >= 0.f) ? v2 : 0.2f*v2;
            cs[tid] = make_float4(v0*cf, v1*cf, v2*cf, 0.f);
        }
        for (int idx = tid; idx < 4096; idx += 256) {
            hs [idx] = g_hw[0][(b*512 + r0)*32 + idx];
            ws2[idx] = g_hw[1][(b*512 + r0)*32 + idx];
        }
        __syncthreads();
        for (int r = 0; r < 128; r++) {
            float4 c4 = cs[r];
            float  hv = hs[r*32 + hh];
            float4 wv = *reinterpret_cast<const float4*>(&ws2[r*32 + ww0]);
            float p;
            p = hv*wv.x; acc[0][0] += p*c4.x; acc[0][1] += p*c4.y; acc[0][2] += p*c4.z;
            p = hv*wv.y; acc[1][0] += p*c4.x; acc[1][1] += p*c4.y; acc[1][2] += p*c4.z;
            p = hv*wv.z; acc[2][0] += p*c4.x; acc[2][1] += p*c4.y; acc[2][2] += p*c4.z;
            p = hv*wv.w; acc[3][0] += p*c4.x; acc[3][1] += p*c4.y; acc[3][2] += p*c4.z;
        }
    }
    #pragma unroll
    for (int c = 0; c < 3; c++)
        #pragma unroll
        for (int i = 0; i < 4; i++)
            out[((b*3 + c)*32 + hh)*32 + ww0 + i] = acc[i][c];
}

// ---------------- launch ----------------
extern "C" void kernel_launch(void* const* d_in, const int* in_sizes, int n_in,
                              void* d_out, int out_size)
{
    const float* noise = (const float*)d_in[0];
    const int*   label = (const int*)  d_in[1];
    const float* lin_w = (const float*)d_in[2];
    const float* bn0_g = (const float*)d_in[4];
    const float* bn0_b = (const float*)d_in[5];
    const float* emb   = (const float*)d_in[6];
    const float* c_w1  = (const float*)d_in[7];
    const float* c_g1  = (const float*)d_in[9];
    const float* c_be1 = (const float*)d_in[10];
    const float* h_w1  = (const float*)d_in[11];
    const float* h_g1  = (const float*)d_in[13];
    const float* h_be1 = (const float*)d_in[14];
    const float* h_w2  = (const float*)d_in[15];
    const float* h_g2  = (const float*)d_in[17];
    const float* h_be2 = (const float*)d_in[18];
    const float* h_w3  = (const float*)d_in[19];
    const float* h_b3  = (const float*)d_in[20];
    const float* w_w1  = (const float*)d_in[21];
    const float* w_g1  = (const float*)d_in[23];
    const float* w_be1 = (const float*)d_in[24];
    const float* w_w2  = (const float*)d_in[25];
    const float* w_g2  = (const float*)d_in[27];
    const float* w_be2 = (const float*)d_in[28];
    const float* w_w3  = (const float*)d_in[29];
    const float* w_b3  = (const float*)d_in[30];
    const float* coef  = (const float*)d_in[31];
    float* out = (float*)d_out;

    const int SMEM = 128*132*4;  // 67584 B (epilogue C buffer)
    cudaFuncSetAttribute(k_conv2f, cudaFuncAttributeMaxDynamicSharedMemorySize, SMEM);
    cudaFuncSetAttribute(k_conv3f, cudaFuncAttributeMaxDynamicSharedMemorySize, SMEM);

    k_combo<<<3328, 256>>>(noise, label, lin_w, bn0_g, bn0_b, emb,
                           h_w2, w_w2, h_w3, w_w3);

    k_gemm1m<<<dim3(32, 4, 3), 256>>>(c_w1, h_w1, w_w1);

    k_prepA2n<<<dim3(256, 2), 256>>>(c_g1, c_be1, h_g1, h_be1, w_g1, w_be1);

    k_conv2f<<<dim3(32, 32, 2), 256, SMEM>>>();

    k_prepA3n<<<dim3(256, 2), 256>>>(h_g2, h_be2, w_g2, w_be2);

    k_conv3f<<<dim3(8, 64, 2), 256, SMEM>>>(h_b3, w_b3);

    k_final<<<256, 256>>>(coef, out);
}

// round 17
// speedup vs baseline: 3.8609x; 3.8609x over previous
#include <cuda_runtime.h>
#include <cuda_bf16.h>
#include <math.h>
#include <stdint.h>

typedef uint32_t u32;

// ---------------- scratch (device globals; no allocation) ----------------
__device__ float g_latT [256*256];
__device__ float g_craw [256*1536];
__device__ float g_x1raw[2][256*2048];
__device__ float g_y2   [2][256*256*31];
__device__ float g_abc  [2][512];
__device__ float g_st1c [2][512];           // conv1 c-branch stat accumulators
__device__ float g_st1hw[2][2][128];        // conv1 h/w stat accumulators
__device__ float g_st2  [2][2][256];        // conv2 stat accumulators
__device__ float g_hw   [2][256*512*32];
// fragment-order bf16 operands: A [mi][ks][lane][4 words], B [ni][ks][lane][2 words]
__device__ __align__(16) u32 g_A2f [2][256*8*32*4];
__device__ __align__(16) u32 g_A2fl[2][256*8*32*4];
__device__ __align__(16) u32 g_B2f [2][512*8*32*2];
__device__ __align__(16) u32 g_B2fl[2][512*8*32*2];
__device__ __align__(16) u32 g_A3f [2][512*16*32*4];
__device__ __align__(16) u32 g_A3fl[2][512*16*32*4];
__device__ __align__(16) u32 g_B3f [2][128*16*32*2];
__device__ __align__(16) u32 g_B3fl[2][128*16*32*2];

__device__ __forceinline__ u32 packbf(float x, float y) {
    __nv_bfloat162 t;
    t.x = __float2bfloat16(x);
    t.y = __float2bfloat16(y);
    return *reinterpret_cast<u32*>(&t);
}
__device__ __forceinline__ void split_pair(float v0, float v1, u32& hw, u32& lw) {
    __nv_bfloat16 h0 = __float2bfloat16(v0), h1 = __float2bfloat16(v1);
    float r0 = v0 - __bfloat162float(h0), r1 = v1 - __bfloat162float(h1);
    __nv_bfloat162 th; th.x = h0; th.y = h1;
    hw = *reinterpret_cast<u32*>(&th);
    lw = packbf(r0, r1);
}
__device__ __forceinline__ void wreduce2(float& s, float& q) {
    #pragma unroll
    for (int o = 16; o > 0; o >>= 1) {
        s += __shfl_xor_sync(0xffffffffu, s, o);
        q += __shfl_xor_sync(0xffffffffu, q, o);
    }
}

#define MMA16816(c, a, b) \
    asm volatile("mma.sync.aligned.m16n8k16.row.col.f32.bf16.bf16.f32 " \
                 "{%0,%1,%2,%3}, {%4,%5,%6,%7}, {%8,%9}, {%0,%1,%2,%3};" \
                 : "+f"((c)[0]), "+f"((c)[1]), "+f"((c)[2]), "+f"((c)[3]) \
                 : "r"((a)[0]), "r"((a)[1]), "r"((a)[2]), "r"((a)[3]), \
                   "r"((b)[0]), "r"((b)[1]))

// ---------------- kernel 1: latent + prepB combo (independent work) ----------------
__global__ __launch_bounds__(256) void k_combo(
    const float* __restrict__ noise, const int* __restrict__ label,
    const float* __restrict__ lin_w, const float* __restrict__ bn0_g,
    const float* __restrict__ bn0_b, const float* __restrict__ emb,
    const float* __restrict__ W2h, const float* __restrict__ W2w,
    const float* __restrict__ W3h, const float* __restrict__ W3w)
{
    const int bid = blockIdx.x, tid = threadIdx.x;
    if (bid < 256) {
        if (bid == 0) {   // zero all stat accumulators (before any producer runs)
            float* p1 = (float*)g_st1c;
            for (int i = tid; i < 1024; i += 256) p1[i] = 0.f;
            float* p2 = (float*)g_st1hw;
            for (int i = tid; i < 512; i += 256) p2[i] = 0.f;
            float* p3 = (float*)g_st2;
            for (int i = tid; i < 1024; i += 256) p3[i] = 0.f;
        }
        // ---- latent ----
        const int ch = bid, b = tid;
        if (ch >= 128) {
            g_latT[ch*256 + b] = emb[label[b]*128 + (ch - 128)];
            return;
        }
        __shared__ float wsm[100];
        if (b < 100) wsm[b] = lin_w[ch*100 + b];
        __syncthreads();
        const float* nr = noise + b*100;
        float z = 0.f;
        #pragma unroll 4
        for (int i = 0; i < 100; i++) z += nr[i]*wsm[i];
        float s = z, q = z*z;
        wreduce2(s, q);
        __shared__ float sp[8], qp[8];
        if ((b & 31) == 0) { sp[b >> 5] = s; qp[b >> 5] = q; }
        __syncthreads();
        float ts = 0.f, tq = 0.f;
        #pragma unroll
        for (int i = 0; i < 8; i++) { ts += sp[i]; tq += qp[i]; }
        float m   = ts*(1.f/256.f);
        float var = tq*(1.f/256.f) - m*m;
        float a   = bn0_g[ch]*rsqrtf(var + 1e-5f);
        float y   = (z - m)*a + bn0_b[ch];
        g_latT[ch*256 + b] = (y >= 0.f) ? y : 0.01f*y;
        return;
    }
    // ---- prepB: weights -> fragment-order bf16 hi/lo (coalesced reads) ----
    int gid = (bid - 256)*256 + tid;
    if (gid < 524288) {                       // W2: 2 br x 64 cp x 4096 n
        int br = gid >> 18, rem = gid & 262143;
        int cp = rem >> 12, n = rem & 4095;
        const float* W = br ? W2w : W2h;      // row-major [ci][4096]
        float v0 = W[(2*cp)*4096 + n];
        float v1 = W[(2*cp + 1)*4096 + n];
        u32 hw, lw; split_pair(v0, v1, hw, lw);
        int ni = n >> 3, ks = cp >> 3, cpl = cp & 7;
        int lane = (n & 7)*4 + (cpl & 3), w = cpl >> 2;
        int addr = ((ni*8 + ks)*32 + lane)*2 + w;
        g_B2f [br][addr] = hw;
        g_B2fl[br][addr] = lw;
    } else {                                  // W3: 2 br x 128 cp x 1024 n
        int g2 = gid - 524288;
        int br = g2 >> 17, rem = g2 & 131071;
        int cp = rem >> 10, n = rem & 1023;
        const float* W = br ? W3w : W3h;      // [ci][1024]
        float v0 = W[(2*cp)*1024 + n];
        float v1 = W[(2*cp + 1)*1024 + n];
        u32 hw, lw; split_pair(v0, v1, hw, lw);
        int ni = n >> 3, ks = cp >> 3, cpl = cp & 7;
        int lane = (n & 7)*4 + (cpl & 3), w = cpl >> 2;
        int addr = ((ni*16 + ks)*32 + lane)*2 + w;
        g_B3f [br][addr] = hw;
        g_B3fl[br][addr] = lw;
    }
}

// ---------------- kernel 2: conv1 GEMMs + fused BN stat partials ----------------
__global__ __launch_bounds__(256) void k_gemm1m(
    const float* __restrict__ Wc, const float* __restrict__ Wh,
    const float* __restrict__ Ww)
{
    const int z = blockIdx.z;
    int N; const float* W; float* O;
    if (z == 2) {
        if (blockIdx.x >= 24) return;
        N = 1536; W = Wc; O = g_craw;
    } else {
        N = 2048; W = z ? Ww : Wh; O = g_x1raw[z];
    }
    const int n0 = blockIdx.x*64, b0 = blockIdx.y*64;
    const int tid = threadIdx.x, tx = tid & 15, ty = tid >> 4;
    __shared__ float Xs[16][68], Ws[16][68];
    __shared__ float cs1[64], cq1[64];
    if (tid < 64) { cs1[tid] = 0.f; cq1[tid] = 0.f; }
    float acc[4][4] = {};
    for (int k0 = 0; k0 < 256; k0 += 16) {
        __syncthreads();
        for (int i = tid; i < 1024; i += 256) {
            int k = i >> 6, c = i & 63;
            Xs[k][c] = g_latT[(k0+k)*256 + b0 + c];
            Ws[k][c] = W[(k0+k)*N + n0 + c];
        }
        __syncthreads();
        #pragma unroll
        for (int k = 0; k < 16; k++) {
            float4 x4 = *(const float4*)&Xs[k][ty*4];
            float4 w4 = *(const float4*)&Ws[k][tx*4];
            float xa[4] = {x4.x, x4.y, x4.z, x4.w};
            float wa[4] = {w4.x, w4.y, w4.z, w4.w};
            #pragma unroll
            for (int i = 0; i < 4; i++)
                #pragma unroll
                for (int j = 0; j < 4; j++) acc[i][j] += xa[i]*wa[j];
        }
    }
    #pragma unroll
    for (int i = 0; i < 4; i++) {
        float4 v = make_float4(acc[i][0], acc[i][1], acc[i][2], acc[i][3]);
        *(float4*)&O[(b0 + ty*4 + i)*N + n0 + tx*4] = v;
    }
    // fused per-channel stat partials
    #pragma unroll
    for (int j = 0; j < 4; j++) {
        float s = acc[0][j] + acc[1][j] + acc[2][j] + acc[3][j];
        float q = acc[0][j]*acc[0][j] + acc[1][j]*acc[1][j]
                + acc[2][j]*acc[2][j] + acc[3][j]*acc[3][j];
        atomicAdd(&cs1[tx*4 + j], s);
        atomicAdd(&cq1[tx*4 + j], q);
    }
    __syncthreads();
    if (tid < 64) {
        int n = n0 + tid;
        if (z == 2) {
            atomicAdd(&g_st1c[0][n/3], cs1[tid]);
            atomicAdd(&g_st1c[1][n/3], cq1[tid]);
        } else {
            atomicAdd(&g_st1hw[z][0][n >> 4], cs1[tid]);
            atomicAdd(&g_st1hw[z][1][n >> 4], cq1[tid]);
        }
    }
}

// ---------------- prepA2: affine from fused stats, smem tile, fragment order --------
// Block (1, 0) additionally materializes the c-branch affine (g_abc) for k_final.
__global__ __launch_bounds__(256) void k_prepA2n(
    const float* __restrict__ cg, const float* __restrict__ cb,
    const float* __restrict__ hg, const float* __restrict__ hb,
    const float* __restrict__ wg, const float* __restrict__ wb)
{
    const int b = blockIdx.x, br = blockIdx.y, tid = threadIdx.x;
    if (b == 1 && br == 0) {
        for (int c = tid; c < 512; c += 256) {
            float s = g_st1c[0][c], q = g_st1c[1][c];
            const float invn = 1.f/(256.f*3.f);
            float m   = s*invn;
            float var = q*invn - m*m;
            float a   = cg[c]*rsqrtf(var + 1e-5f);
            g_abc[0][c] = a;
            g_abc[1][c] = cb[c] - m*a;
        }
    }
    __shared__ float xs[128*17];     // [ci*17 + l], padded
    __shared__ float aAs[128], aSs[128];
    if (tid < 128) {
        float s = g_st1hw[br][0][tid], q = g_st1hw[br][1][tid];
        const float invn = 1.f/(256.f*16.f);
        float m   = s*invn;
        float var = q*invn - m*m;
        float gam = br ? wg[tid] : hg[tid];
        float bet = br ? wb[tid] : hb[tid];
        float a   = gam*rsqrtf(var + 1e-5f);
        aAs[tid] = a;
        aSs[tid] = bet - m*a;
    }
    for (int idx = tid; idx < 2048; idx += 256) {
        float v = g_x1raw[br][b*2048 + idx];
        xs[(idx >> 4)*17 + (idx & 15)] = v;
    }
    __syncthreads();
    const int ks = tid >> 5, lane = tid & 31;
    u32 oh[4], ol[4];
    #pragma unroll
    for (int w = 0; w < 4; w++) {
        int cpl2 = w >> 1, l3 = w & 1;
        int l   = (l3 << 3) | (lane >> 2);
        int cpl = (cpl2 << 2) | (lane & 3);
        int ci  = (ks*8 + cpl)*2;
        float v0 = fmaf(aAs[ci],   xs[ci*17 + l],     aSs[ci]);
        float v1 = fmaf(aAs[ci+1], xs[(ci+1)*17 + l], aSs[ci+1]);
        v0 = (v0 >= 0.f) ? v0 : 0.2f*v0;
        v1 = (v1 >= 0.f) ? v1 : 0.2f*v1;
        split_pair(v0, v1, oh[w], ol[w]);
    }
    int addr = ((b*8 + ks)*32 + lane)*4;
    *(uint4*)&g_A2f [br][addr] = make_uint4(oh[0], oh[1], oh[2], oh[3]);
    *(uint4*)&g_A2fl[br][addr] = make_uint4(ol[0], ol[1], ol[2], ol[3]);
}

// ---------------- conv2: fragment-direct mma.sync + fused BN stat partials ----------
extern __shared__ u32 smw[];
__global__ __launch_bounds__(256, 2) void k_conv2f()
{
    const int br = blockIdx.z, nx = blockIdx.x, my = blockIdx.y;
    const int tid = threadIdx.x, lane = tid & 31, wid = tid >> 5;
    const int wm = wid >> 2, wn = wid & 3;
    const u32* __restrict__ AH = g_A2f [br];
    const u32* __restrict__ AL = g_A2fl[br];
    const u32* __restrict__ BH = g_B2f [br];
    const u32* __restrict__ BL = g_B2fl[br];
    const int mi0 = my*8 + wm*4;
    const int ni0 = nx*16 + wn*4;
    float acc[4][4][4] = {};
    #pragma unroll
    for (int ks = 0; ks < 8; ks++) {
        u32 bh[4][2], bl[4][2];
        #pragma unroll
        for (int nt = 0; nt < 4; nt++) {
            int ba = (((ni0+nt)*8 + ks)*32 + lane)*2;
            uint2 vh = *(const uint2*)(BH + ba); bh[nt][0] = vh.x; bh[nt][1] = vh.y;
            uint2 vl = *(const uint2*)(BL + ba); bl[nt][0] = vl.x; bl[nt][1] = vl.y;
        }
        #pragma unroll
        for (int mt = 0; mt < 4; mt++) {
            int aa = (((mi0+mt)*8 + ks)*32 + lane)*4;
            uint4 vh = *(const uint4*)(AH + aa);
            uint4 vl = *(const uint4*)(AL + aa);
            u32 ah[4] = {vh.x, vh.y, vh.z, vh.w};
            u32 al[4] = {vl.x, vl.y, vl.z, vl.w};
            #pragma unroll
            for (int nt = 0; nt < 4; nt++) {
                MMA16816(acc[mt][nt], ah, bh[nt]);
                MMA16816(acc[mt][nt], ah, bl[nt]);
                MMA16816(acc[mt][nt], al, bh[nt]);
            }
        }
    }
    float* Cs = (float*)smw;                    // 128 x 132
    const int qr = lane >> 2, qt = lane & 3;
    #pragma unroll
    for (int mt = 0; mt < 4; mt++)
        #pragma unroll
        for (int nt = 0; nt < 4; nt++) {
            int r0 = wm*64 + mt*16 + qr, c0 = wn*32 + nt*8 + qt*2;
            Cs[r0*132 + c0]       = acc[mt][nt][0];
            Cs[r0*132 + c0 + 1]   = acc[mt][nt][1];
            Cs[(r0+8)*132 + c0]   = acc[mt][nt][2];
            Cs[(r0+8)*132 + c0+1] = acc[mt][nt][3];
        }
    __syncthreads();
    // epilogue: warp w owns output channel co_l = w; fold, write y2, stat partials.
    {
        const int co_l = wid;
        float ssum = 0.f, sq = 0.f;
        for (int i = lane; i < 248; i += 32) {
            int bl2 = i / 31, t = i - bl2*31;
            int lo = (t > 15) ? (t - 15) : 0;
            int hi = (t < 15) ? t : 15;
            float s = 0.f;
            for (int tp = lo; tp <= hi; tp++)
                s += Cs[(bl2*16 + tp)*132 + co_l*16 + (t - tp)];
            g_y2[br][((my*8 + bl2)*256 + nx*8 + co_l)*31 + t] = s;
            ssum += s; sq += s*s;
        }
        wreduce2(ssum, sq);
        if (lane == 0) {
            atomicAdd(&g_st2[br][0][nx*8 + co_l], ssum);
            atomicAdd(&g_st2[br][1][nx*8 + co_l], sq);
        }
    }
}

// ---------------- prepA3: affine from fused stats, smem tile, fragment order ------
__global__ __launch_bounds__(256) void k_prepA3n(
    const float* __restrict__ hg, const float* __restrict__ hb,
    const float* __restrict__ wg, const float* __restrict__ wb)
{
    const int b = blockIdx.x, br = blockIdx.y, tid = threadIdx.x;
    __shared__ float ys[256*33];     // [ci*33 + t], padded
    __shared__ float aAs[256], aSs[256];
    {   // derive BN affine from accumulated stats
        float s = g_st2[br][0][tid], q = g_st2[br][1][tid];
        const float inv = 1.f/(256.f*31.f);
        float m   = s*inv;
        float var = q*inv - m*m;
        float gam = br ? wg[tid] : hg[tid];
        float bet = br ? wb[tid] : hb[tid];
        float a   = gam*rsqrtf(var + 1e-5f);
        aAs[tid] = a;
        aSs[tid] = bet - m*a;
    }
    for (int idx = tid; idx < 7936; idx += 256) {
        float v = g_y2[br][b*7936 + idx];
        ys[(idx / 31)*33 + (idx % 31)] = v;
    }
    __syncthreads();
    const int lane = tid & 31;
    #pragma unroll
    for (int it = 0; it < 2; it++) {
        const int ks = (tid >> 5) + 8*it;
        #pragma unroll
        for (int mih = 0; mih < 2; mih++) {
            u32 oh[4], ol[4];
            #pragma unroll
            for (int w = 0; w < 4; w++) {
                int cpl2 = w >> 1, r3 = w & 1;
                int r   = (r3 << 3) | (lane >> 2);
                int tp  = (mih << 4) | r;
                int cpl = (cpl2 << 2) | (lane & 3);
                int ci  = (ks*8 + cpl)*2;
                float v0 = 0.f, v1 = 0.f;
                if (tp < 31) {
                    v0 = fmaf(aAs[ci],   ys[ci*33 + tp],     aSs[ci]);
                    v1 = fmaf(aAs[ci+1], ys[(ci+1)*33 + tp], aSs[ci+1]);
                    v0 = (v0 >= 0.f) ? v0 : 0.2f*v0;
                    v1 = (v1 >= 0.f) ? v1 : 0.2f*v1;
                }
                split_pair(v0, v1, oh[w], ol[w]);
            }
            int mi = b*2 + mih;
            int addr = ((mi*16 + ks)*32 + lane)*4;
            *(uint4*)&g_A3f [br][addr] = make_uint4(oh[0], oh[1], oh[2], oh[3]);
            *(uint4*)&g_A3fl[br][addr] = make_uint4(ol[0], ol[1], ol[2], ol[3]);
        }
    }
}

// ---------------- conv3: fragment-direct mma.sync, fold + bias + tanh ------
__global__ __launch_bounds__(256, 2) void k_conv3f(
    const float* __restrict__ bh3, const float* __restrict__ bw3)
{
    const int br = blockIdx.z, nx = blockIdx.x, my = blockIdx.y;
    const float* __restrict__ bias = br ? bw3 : bh3;
    const int tid = threadIdx.x, lane = tid & 31, wid = tid >> 5;
    const int wm = wid >> 2, wn = wid & 3;
    const u32* __restrict__ AH = g_A3f [br];
    const u32* __restrict__ AL = g_A3fl[br];
    const u32* __restrict__ BH = g_B3f [br];
    const u32* __restrict__ BL = g_B3fl[br];
    const int mi0 = my*8 + wm*4;
    const int ni0 = nx*16 + wn*4;
    float acc[4][4][4] = {};
    #pragma unroll
    for (int ks = 0; ks < 16; ks++) {
        u32 bh[4][2], bl[4][2];
        #pragma unroll
        for (int nt = 0; nt < 4; nt++) {
            int ba = (((ni0+nt)*16 + ks)*32 + lane)*2;
            uint2 vh = *(const uint2*)(BH + ba); bh[nt][0] = vh.x; bh[nt][1] = vh.y;
            uint2 vl = *(const uint2*)(BL + ba); bl[nt][0] = vl.x; bl[nt][1] = vl.y;
        }
        #pragma unroll
        for (int mt = 0; mt < 4; mt++) {
            int aa = (((mi0+mt)*16 + ks)*32 + lane)*4;
            uint4 vh = *(const uint4*)(AH + aa);
            uint4 vl = *(const uint4*)(AL + aa);
            u32 ah[4] = {vh.x, vh.y, vh.z, vh.w};
            u32 al[4] = {vl.x, vl.y, vl.z, vl.w};
            #pragma unroll
            for (int nt = 0; nt < 4; nt++) {
                MMA16816(acc[mt][nt], ah, bh[nt]);
                MMA16816(acc[mt][nt], ah, bl[nt]);
                MMA16816(acc[mt][nt], al, bh[nt]);
            }
        }
    }
    float* Cs = (float*)smw;                    // 128 x 132
    const int qr = lane >> 2, qt = lane & 3;
    #pragma unroll
    for (int mt = 0; mt < 4; mt++)
        #pragma unroll
        for (int nt = 0; nt < 4; nt++) {
            int r0 = wm*64 + mt*16 + qr, c0 = wn*32 + nt*8 + qt*2;
            Cs[r0*132 + c0]       = acc[mt][nt][0];
            Cs[r0*132 + c0 + 1]   = acc[mt][nt][1];
            Cs[(r0+8)*132 + c0]   = acc[mt][nt][2];
            Cs[(r0+8)*132 + c0+1] = acc[mt][nt][3];
        }
    __syncthreads();
    // rows: bl*32 + t' (4 b per CTA), cols: co_l*2 + k (64 co per CTA)
    for (int i = 0; i < 32; i++) {
        int idx = tid + i*256;                  // 8192 outputs
        int t = idx & 31, co_l = (idx >> 5) & 63, bl2 = idx >> 11;
        int row = bl2*32 + t;
        float v = Cs[row*132 + 2*co_l];
        if (t > 0) v += Cs[(row-1)*132 + 2*co_l + 1];
        v += bias[nx*64 + co_l];
        g_hw[br][((my*4 + bl2)*512 + nx*64 + co_l)*32 + t] = tanhf(v);
    }
}

// ---------------- kernel: final einsum ----------------
__global__ __launch_bounds__(256) void k_final(const float* __restrict__ coef,
                                               float* __restrict__ out)
{
    const int b = blockIdx.x, tid = threadIdx.x;
    __shared__ __align__(16) float4 cs[128];
    __shared__ __align__(16) float  hs [128*32];
    __shared__ __align__(16) float  ws2[128*32];
    const int p0 = tid*4, hh = p0 >> 5, ww0 = p0 & 31;
    float acc[4][3];
    #pragma unroll
    for (int i = 0; i < 4; i++)
        #pragma unroll
        for (int c = 0; c < 3; c++) acc[i][c] = 0.f;
    for (int chk = 0; chk < 4; chk++) {
        const int r0 = chk*128;
        __syncthreads();
        if (tid < 128) {
            const int r = r0 + tid;
            const float* cp = g_craw + b*1536 + r*3;
            float a = g_abc[0][r], sh = g_abc[1][r];
            float cf = coef[r];
            float v0 = fmaf(a, cp[0], sh); v0 = (v0 >= 0.f) ? v0 : 0.2f*v0;
            float v1 = fmaf(a, cp[1], sh); v1 = (v1 >= 0.f) ? v1 : 0.2f*v1;
            float v2 = fmaf(a, cp[2], sh); v2 = (v2 >= 0.f) ? v2 : 0.2f*v2;
            cs[tid] = make_float4(v0*cf, v1*cf, v2*cf, 0.f);
        }
        for (int idx = tid; idx < 4096; idx += 256) {
            hs [idx] = g_hw[0][(b*512 + r0)*32 + idx];
            ws2[idx] = g_hw[1][(b*512 + r0)*32 + idx];
        }
        __syncthreads();
        for (int r = 0; r < 128; r++) {
            float4 c4 = cs[r];
            float  hv = hs[r*32 + hh];
            float4 wv = *reinterpret_cast<const float4*>(&ws2[r*32 + ww0]);
            float p;
            p = hv*wv.x; acc[0][0] += p*c4.x; acc[0][1] += p*c4.y; acc[0][2] += p*c4.z;
            p = hv*wv.y; acc[1][0] += p*c4.x; acc[1][1] += p*c4.y; acc[1][2] += p*c4.z;
            p = hv*wv.z; acc[2][0] += p*c4.x; acc[2][1] += p*c4.y; acc[2][2] += p*c4.z;
            p = hv*wv.w; acc[3][0] += p*c4.x; acc[3][1] += p*c4.y; acc[3][2] += p*c4.z;
        }
    }
    #pragma unroll
    for (int c = 0; c < 3; c++)
        #pragma unroll
        for (int i = 0; i < 4; i++)
            out[((b*3 + c)*32 + hh)*32 + ww0 + i] = acc[i][c];
}

// ---------------- launch ----------------
extern "C" void kernel_launch(void* const* d_in, const int* in_sizes, int n_in,
                              void* d_out, int out_size)
{
    const float* noise = (const float*)d_in[0];
    const int*   label = (const int*)  d_in[1];
    const float* lin_w = (const float*)d_in[2];
    const float* bn0_g = (const float*)d_in[4];
    const float* bn0_b = (const float*)d_in[5];
    const float* emb   = (const float*)d_in[6];
    const float* c_w1  = (const float*)d_in[7];
    const float* c_g1  = (const float*)d_in[9];
    const float* c_be1 = (const float*)d_in[10];
    const float* h_w1  = (const float*)d_in[11];
    const float* h_g1  = (const float*)d_in[13];
    const float* h_be1 = (const float*)d_in[14];
    const float* h_w2  = (const float*)d_in[15];
    const float* h_g2  = (const float*)d_in[17];
    const float* h_be2 = (const float*)d_in[18];
    const float* h_w3  = (const float*)d_in[19];
    const float* h_b3  = (const float*)d_in[20];
    const float* w_w1  = (const float*)d_in[21];
    const float* w_g1  = (const float*)d_in[23];
    const float* w_be1 = (const float*)d_in[24];
    const float* w_w2  = (const float*)d_in[25];
    const float* w_g2  = (const float*)d_in[27];
    const float* w_be2 = (const float*)d_in[28];
    const float* w_w3  = (const float*)d_in[29];
    const float* w_b3  = (const float*)d_in[30];
    const float* coef  = (const float*)d_in[31];
    float* out = (float*)d_out;

    const int SMEM = 128*132*4;  // 67584 B (epilogue C buffer)
    cudaFuncSetAttribute(k_conv2f, cudaFuncAttributeMaxDynamicSharedMemorySize, SMEM);
    cudaFuncSetAttribute(k_conv3f, cudaFuncAttributeMaxDynamicSharedMemorySize, SMEM);

    k_combo<<<3328, 256>>>(noise, label, lin_w, bn0_g, bn0_b, emb,
                           h_w2, w_w2, h_w3, w_w3);

    k_gemm1m<<<dim3(32, 4, 3), 256>>>(c_w1, h_w1, w_w1);

    k_prepA2n<<<dim3(256, 2), 256>>>(c_g1, c_be1, h_g1, h_be1, w_g1, w_be1);

    k_conv2f<<<dim3(32, 32, 2), 256, SMEM>>>();

    k_prepA3n<<<dim3(256, 2), 256>>>(h_g2, h_be2, w_g2, w_be2);

    k_conv3f<<<dim3(8, 64, 2), 256, SMEM>>>(h_b3, w_b3);

    k_final<<<256, 256>>>(coef, out);
}